// round 1
// baseline (speedup 1.0000x reference)
#include <cuda_runtime.h>
#include <cuda_bf16.h>
#include <math.h>

// ---------------- problem constants ----------------
#define B_Q     1024      // queries
#define DM      4096      // model dim
#define NH      32        // q heads
#define NKV     8         // kv heads
#define HD      128       // head dim
#define PAST    4096      // past cache length
#define SINKS_N 4
#define SCALE_QK 0.08838834764831845f   // 1/sqrt(128)

// ---------------- scratch (device globals; no allocation allowed) ----------------
__device__ float g_qbuf[B_Q * NH * HD];    // [Q][H*D]   post-GEMM, pre-RoPE
__device__ float g_kbuf[B_Q * NKV * HD];   // [Q][Hkv*D]
__device__ float g_vbuf[B_Q * NKV * HD];   // [Q][Hkv*D]
__device__ float g_qt[NH * B_Q * HD];      // [H][Q][D]  post-RoPE
__device__ float g_kt[NKV * B_Q * HD];     // [Hkv][Q][D] post-RoPE
__device__ float g_vt[NKV * B_Q * HD];     // [Hkv][Q][D]
__device__ float g_attn[B_Q * NH * HD];    // [Q][H*D]   attention output

// ---------------- SGEMM: C[M,N] = A[M,K] @ B[K,N], all row-major ----------------
// 128x128 block tile, 8x8 per-thread microtile, K-step 8, 256 threads.
__global__ __launch_bounds__(256) void sgemm_kernel(
    const float* __restrict__ A, const float* __restrict__ B,
    float* __restrict__ C, int M, int N, int K)
{
    __shared__ float As[8][132];   // k-major, padded (conflict-free scatter store)
    __shared__ float Bs[8][128];

    const int tid = threadIdx.x;
    const int tx  = tid & 15;
    const int ty  = tid >> 4;
    const int m0  = blockIdx.y * 128;
    const int n0  = blockIdx.x * 128;

    // loader mapping
    const int arow  = tid >> 1;          // 0..127
    const int acol4 = (tid & 1) * 4;     // 0 or 4
    const int brow  = tid >> 5;          // 0..7
    const int bcol4 = (tid & 31) * 4;    // 0..124

    const float* Ap = A + (size_t)(m0 + arow) * K + acol4;
    const float* Bp = B + (size_t)brow * N + n0 + bcol4;

    float acc[8][8];
#pragma unroll
    for (int i = 0; i < 8; i++)
#pragma unroll
        for (int j = 0; j < 8; j++) acc[i][j] = 0.f;

    for (int k0 = 0; k0 < K; k0 += 8) {
        float4 av = *(const float4*)(Ap + k0);
        float4 bv = *(const float4*)(Bp + (size_t)k0 * N);
        As[acol4 + 0][arow] = av.x;
        As[acol4 + 1][arow] = av.y;
        As[acol4 + 2][arow] = av.z;
        As[acol4 + 3][arow] = av.w;
        *(float4*)&Bs[brow][bcol4] = bv;
        __syncthreads();

#pragma unroll
        for (int kk = 0; kk < 8; kk++) {
            float a[8], b[8];
            *(float4*)(a)     = *(const float4*)&As[kk][ty * 8];
            *(float4*)(a + 4) = *(const float4*)&As[kk][ty * 8 + 4];
            *(float4*)(b)     = *(const float4*)&Bs[kk][tx * 8];
            *(float4*)(b + 4) = *(const float4*)&Bs[kk][tx * 8 + 4];
#pragma unroll
            for (int i = 0; i < 8; i++)
#pragma unroll
                for (int j = 0; j < 8; j++)
                    acc[i][j] += a[i] * b[j];
        }
        __syncthreads();
    }

#pragma unroll
    for (int i = 0; i < 8; i++) {
        float* cp = C + (size_t)(m0 + ty * 8 + i) * N + n0 + tx * 8;
        *(float4*)cp       = make_float4(acc[i][0], acc[i][1], acc[i][2], acc[i][3]);
        *(float4*)(cp + 4) = make_float4(acc[i][4], acc[i][5], acc[i][6], acc[i][7]);
    }
}

// ---------------- RoPE + transpose to head-major ----------------
// grid (Q, 48): slot<32 -> q head, <40 -> k head, else v head. 128 threads (d).
__global__ void rope_kernel(const float* __restrict__ cosT, const float* __restrict__ sinT)
{
    const int qi   = blockIdx.x;
    const int slot = blockIdx.y;
    const int d    = threadIdx.x;
    const int pos  = PAST + qi;
    const float c = cosT[pos * HD + d];
    const float s = sinT[pos * HD + d];

    if (slot < NH) {
        const int h = slot;
        const float* src = g_qbuf + (size_t)qi * (NH * HD) + h * HD;
        float x = src[d], y = src[d ^ 64];
        float r = x * c + ((d < 64) ? -y : y) * s;
        g_qt[((size_t)h * B_Q + qi) * HD + d] = r;
    } else if (slot < NH + NKV) {
        const int h = slot - NH;
        const float* src = g_kbuf + (size_t)qi * (NKV * HD) + h * HD;
        float x = src[d], y = src[d ^ 64];
        float r = x * c + ((d < 64) ? -y : y) * s;
        g_kt[((size_t)h * B_Q + qi) * HD + d] = r;
    } else {
        const int h = slot - NH - NKV;
        g_vt[((size_t)h * B_Q + qi) * HD + d] =
            g_vbuf[(size_t)qi * (NKV * HD) + h * HD + d];
    }
}

// ---------------- Flash attention ----------------
// grid (16 qtiles, 32 heads), 256 threads as 16x16, Q-tile 64, K-tile 128.
// Kept keys: key_pos[j] = j<4 ? j : j+1024 (j in [0,4096)); mask: j <= 3072+qi.
// Thread (tx,ty): S rows ty*4+i (i<4), S cols tx*8+j (j<8); O rows same, cols tx*8+j.
__global__ __launch_bounds__(256) void attn_kernel(
    const float* __restrict__ past_k, const float* __restrict__ past_v)
{
    extern __shared__ float sm[];
    float* Qs = sm;                  // [128 d][68]   (64 rows + pad)
    float* Ks = Qs + 128 * 68;       // [128 d][132]  (128 keys + pad)
    float* Vs = Ks + 128 * 132;      // [128 key][132] (128 dims + pad)
    float* Ps = Vs + 128 * 132;      // [128 key][68] (64 rows + pad)

    const int tid   = threadIdx.x;
    const int tx    = tid & 15;
    const int ty    = tid >> 4;
    const int qtile = blockIdx.x;
    const int h     = blockIdx.y;
    const int kvh   = h >> 2;
    const int q0    = qtile * 64;

    // load Q tile (transposed: d-major)
#pragma unroll
    for (int p = 0; p < 32; p++) {
        int e = p * 256 + tid;
        int row = e >> 7, d = e & 127;
        Qs[d * 68 + row] = g_qt[((size_t)h * B_Q + q0 + row) * HD + d];
    }

    float m_i[4], l_i[4], o[4][8];
#pragma unroll
    for (int i = 0; i < 4; i++) {
        m_i[i] = -1e30f; l_i[i] = 0.f;
#pragma unroll
        for (int j = 0; j < 8; j++) o[i][j] = 0.f;
    }

    const int ntiles = ((3072 + q0 + 63) >> 7) + 1;   // causal skip of dead tiles

    for (int kt = 0; kt < ntiles; kt++) {
        const int jbase = kt * 128;
        __syncthreads();   // prior iteration's PV done before overwriting Ks/Vs/Ps

        // K tile -> transposed smem (scalar, coalesced global reads)
#pragma unroll
        for (int p = 0; p < 64; p++) {
            int e = p * 256 + tid;
            int key = e >> 7, d = e & 127;
            int j = jbase + key;
            int kp = (j < SINKS_N) ? j : j + 1024;
            float v = (kp < PAST)
                ? past_k[((size_t)kvh * PAST + kp) * HD + d]
                : g_kt[((size_t)kvh * B_Q + (kp - PAST)) * HD + d];
            Ks[d * 132 + key] = v;
        }
        // V tile (natural layout, float4)
#pragma unroll
        for (int p = 0; p < 16; p++) {
            int e = p * 256 + tid;
            int key = e >> 5, dc = e & 31;
            int j = jbase + key;
            int kp = (j < SINKS_N) ? j : j + 1024;
            float4 v = (kp < PAST)
                ? *(const float4*)&past_v[((size_t)kvh * PAST + kp) * HD + dc * 4]
                : *(const float4*)&g_vt[((size_t)kvh * B_Q + (kp - PAST)) * HD + dc * 4];
            *(float4*)&Vs[key * 132 + dc * 4] = v;
        }
        __syncthreads();

        // S = Q @ K^T  (4x8 microtile)
        float s[4][8];
#pragma unroll
        for (int i = 0; i < 4; i++)
#pragma unroll
            for (int j = 0; j < 8; j++) s[i][j] = 0.f;

#pragma unroll 8
        for (int kk = 0; kk < 128; kk++) {
            float4 a  = *(const float4*)&Qs[kk * 68 + ty * 4];
            float4 b0 = *(const float4*)&Ks[kk * 132 + tx * 8];
            float4 b1 = *(const float4*)&Ks[kk * 132 + tx * 8 + 4];
            float av[4] = {a.x, a.y, a.z, a.w};
            float bv[8] = {b0.x, b0.y, b0.z, b0.w, b1.x, b1.y, b1.z, b1.w};
#pragma unroll
            for (int i = 0; i < 4; i++)
#pragma unroll
                for (int j = 0; j < 8; j++)
                    s[i][j] += av[i] * bv[j];
        }

        // online softmax (row stats register-resident; rows live in one warp half)
#pragma unroll
        for (int i = 0; i < 4; i++) {
            const int lim = 3072 + q0 + ty * 4 + i;
            float mx = -1e30f;
#pragma unroll
            for (int j = 0; j < 8; j++) {
                int jg = jbase + tx * 8 + j;
                float v = (jg <= lim) ? s[i][j] * SCALE_QK : -1e30f;
                s[i][j] = v;
                mx = fmaxf(mx, v);
            }
#pragma unroll
            for (int off = 1; off < 16; off <<= 1)
                mx = fmaxf(mx, __shfl_xor_sync(0xffffffffu, mx, off));
            float mnew = fmaxf(m_i[i], mx);
            float corr = __expf(m_i[i] - mnew);
            m_i[i] = mnew;
            float rs = 0.f;
#pragma unroll
            for (int j = 0; j < 8; j++) {
                float p = __expf(s[i][j] - mnew);
                rs += p;
                Ps[(tx * 8 + j) * 68 + ty * 4 + i] = p;
            }
#pragma unroll
            for (int off = 1; off < 16; off <<= 1)
                rs += __shfl_xor_sync(0xffffffffu, rs, off);
            l_i[i] = l_i[i] * corr + rs;
#pragma unroll
            for (int j = 0; j < 8; j++) o[i][j] *= corr;
        }
        __syncthreads();   // Ps visible

        // O += P @ V
#pragma unroll 8
        for (int kk = 0; kk < 128; kk++) {
            float4 a  = *(const float4*)&Ps[kk * 68 + ty * 4];
            float4 b0 = *(const float4*)&Vs[kk * 132 + tx * 8];
            float4 b1 = *(const float4*)&Vs[kk * 132 + tx * 8 + 4];
            float av[4] = {a.x, a.y, a.z, a.w};
            float bv[8] = {b0.x, b0.y, b0.z, b0.w, b1.x, b1.y, b1.z, b1.w};
#pragma unroll
            for (int i = 0; i < 4; i++)
#pragma unroll
                for (int j = 0; j < 8; j++)
                    o[i][j] += av[i] * bv[j];
        }
    }

    // epilogue: normalize + store [Q][H*D]
#pragma unroll
    for (int i = 0; i < 4; i++) {
        float inv = 1.0f / l_i[i];
        int row = q0 + ty * 4 + i;
        float* dst = g_attn + (size_t)row * (NH * HD) + h * HD + tx * 8;
        *(float4*)dst       = make_float4(o[i][0] * inv, o[i][1] * inv, o[i][2] * inv, o[i][3] * inv);
        *(float4*)(dst + 4) = make_float4(o[i][4] * inv, o[i][5] * inv, o[i][6] * inv, o[i][7] * inv);
    }
}

// ---------------- launch ----------------
extern "C" void kernel_launch(void* const* d_in, const int* in_sizes, int n_in,
                              void* d_out, int out_size)
{
    (void)in_sizes; (void)n_in; (void)out_size;
    const float* hidden = (const float*)d_in[0];
    const float* Wq     = (const float*)d_in[1];
    const float* Wk     = (const float*)d_in[2];
    const float* Wv     = (const float*)d_in[3];
    const float* Wo     = (const float*)d_in[4];
    const float* past_k = (const float*)d_in[5];
    const float* past_v = (const float*)d_in[6];
    const float* cosT   = (const float*)d_in[7];
    const float* sinT   = (const float*)d_in[8];
    // d_in[9] = position_ids (arange(Q)); structure folded into the kernels.

    void *p_qbuf, *p_kbuf, *p_vbuf, *p_attn;
    cudaGetSymbolAddress(&p_qbuf, g_qbuf);
    cudaGetSymbolAddress(&p_kbuf, g_kbuf);
    cudaGetSymbolAddress(&p_vbuf, g_vbuf);
    cudaGetSymbolAddress(&p_attn, g_attn);

    const int attn_smem = (128 * 68 + 128 * 132 + 128 * 132 + 128 * 68) * 4;  // 204800 B
    cudaFuncSetAttribute(attn_kernel, cudaFuncAttributeMaxDynamicSharedMemorySize, attn_smem);

    dim3 blk(256);
    // QKV projections
    sgemm_kernel<<<dim3(DM / 128, B_Q / 128), blk>>>(hidden, Wq, (float*)p_qbuf, B_Q, DM, DM);
    sgemm_kernel<<<dim3((NKV * HD) / 128, B_Q / 128), blk>>>(hidden, Wk, (float*)p_kbuf, B_Q, NKV * HD, DM);
    sgemm_kernel<<<dim3((NKV * HD) / 128, B_Q / 128), blk>>>(hidden, Wv, (float*)p_vbuf, B_Q, NKV * HD, DM);
    // RoPE + transpose
    rope_kernel<<<dim3(B_Q, NH + 2 * NKV), 128>>>(cosT, sinT);
    // attention
    attn_kernel<<<dim3(B_Q / 64, NH), blk, attn_smem>>>(past_k, past_v);
    // output projection -> d_out
    sgemm_kernel<<<dim3(DM / 128, B_Q / 128), blk>>>((const float*)p_attn, Wo, (float*)d_out, B_Q, DM, NH * HD);
}

// round 3
// speedup vs baseline: 2.0567x; 2.0567x over previous
#include <cuda_runtime.h>
#include <cuda_bf16.h>
#include <math.h>

// ---------------- problem constants ----------------
#define B_Q     1024
#define DM      4096
#define NH      32
#define NKV     8
#define HD      128
#define PAST    4096
#define SINKS_N 4
#define SCALE_QK 0.08838834764831845f   // 1/sqrt(128)

// ---------------- scratch ----------------
__device__ float g_qbuf[B_Q * NH * HD];
__device__ float g_kbuf[B_Q * NKV * HD];
__device__ float g_vbuf[B_Q * NKV * HD];
__device__ float g_qt[NH * B_Q * HD];
__device__ float g_kt[NKV * B_Q * HD];
__device__ float g_vt[NKV * B_Q * HD];
__device__ float g_attn[B_Q * NH * HD];

// ---------------- helpers ----------------
__device__ __forceinline__ unsigned f2tf(float x) {
    unsigned u; asm("cvt.rna.tf32.f32 %0, %1;" : "=r"(u) : "f"(x)); return u;
}
__device__ __forceinline__ float f2tff(float x) { return __uint_as_float(f2tf(x)); }

__device__ __forceinline__ void mma_tf32(float d[4],
    unsigned a0, unsigned a1, unsigned a2, unsigned a3,
    unsigned b0, unsigned b1)
{
    asm volatile(
        "mma.sync.aligned.m16n8k8.row.col.f32.tf32.tf32.f32 "
        "{%0,%1,%2,%3},{%4,%5,%6,%7},{%8,%9},{%0,%1,%2,%3};"
        : "+f"(d[0]), "+f"(d[1]), "+f"(d[2]), "+f"(d[3])
        : "r"(a0), "r"(a1), "r"(a2), "r"(a3), "r"(b0), "r"(b1));
}

// ---------------- tf32 tensor-core SGEMM ----------------
// C[M,N] = A[M,K] @ B[K,N] row-major. Block 128x128, k-step 32, 8 warps (2x4),
// warp tile 64x32 = 4x4 mma tiles of m16n8k8. Warp tiles disjoint -> no
// cross-warp state.
__global__ __launch_bounds__(256, 2) void sgemm_tc(
    const float* __restrict__ A, const float* __restrict__ B,
    float* __restrict__ C, int M, int N, int K)
{
    __shared__ float As[128][36];
    __shared__ float Bs[32][132];

    const int tid  = threadIdx.x;
    const int w    = tid >> 5, lane = tid & 31;
    const int g    = lane >> 2, cq = lane & 3;
    const int wm   = w & 1, wn = w >> 1;
    const int m0   = blockIdx.y * 128, n0 = blockIdx.x * 128;

    const int ar  = tid >> 3, ac4 = (tid & 7) * 4;
    const int bkr = tid >> 5, bn4 = (tid & 31) * 4;

    float acc[4][4][4];
#pragma unroll
    for (int i = 0; i < 4; i++)
#pragma unroll
        for (int j = 0; j < 4; j++)
#pragma unroll
            for (int r = 0; r < 4; r++) acc[i][j][r] = 0.f;

    for (int k0 = 0; k0 < K; k0 += 32) {
        __syncthreads();
#pragma unroll
        for (int i = 0; i < 4; i++) {
            float4 v = *(const float4*)&A[(size_t)(m0 + ar + i * 32) * K + k0 + ac4];
            *(float4*)&As[ar + i * 32][ac4] =
                make_float4(f2tff(v.x), f2tff(v.y), f2tff(v.z), f2tff(v.w));
        }
#pragma unroll
        for (int i = 0; i < 4; i++) {
            float4 v = *(const float4*)&B[(size_t)(k0 + bkr + i * 8) * N + n0 + bn4];
            *(float4*)&Bs[bkr + i * 8][bn4] =
                make_float4(f2tff(v.x), f2tff(v.y), f2tff(v.z), f2tff(v.w));
        }
        __syncthreads();

#pragma unroll
        for (int ks = 0; ks < 4; ks++) {
            unsigned a[4][4], b[4][2];
            const int k = ks * 8 + cq;
#pragma unroll
            for (int mt = 0; mt < 4; mt++) {
                int r = wm * 64 + mt * 16 + g;
                a[mt][0] = __float_as_uint(As[r][k]);
                a[mt][1] = __float_as_uint(As[r + 8][k]);
                a[mt][2] = __float_as_uint(As[r][k + 4]);
                a[mt][3] = __float_as_uint(As[r + 8][k + 4]);
            }
#pragma unroll
            for (int nt = 0; nt < 4; nt++) {
                int n = wn * 32 + nt * 8 + g;
                b[nt][0] = __float_as_uint(Bs[k][n]);
                b[nt][1] = __float_as_uint(Bs[k + 4][n]);
            }
#pragma unroll
            for (int mt = 0; mt < 4; mt++)
#pragma unroll
                for (int nt = 0; nt < 4; nt++)
                    mma_tf32(acc[mt][nt], a[mt][0], a[mt][1], a[mt][2], a[mt][3],
                             b[nt][0], b[nt][1]);
        }
    }

#pragma unroll
    for (int mt = 0; mt < 4; mt++)
#pragma unroll
        for (int nt = 0; nt < 4; nt++) {
            int r  = m0 + wm * 64 + mt * 16 + g;
            int cc = n0 + wn * 32 + nt * 8 + 2 * cq;
            *(float2*)&C[(size_t)r * N + cc]       = make_float2(acc[mt][nt][0], acc[mt][nt][1]);
            *(float2*)&C[(size_t)(r + 8) * N + cc] = make_float2(acc[mt][nt][2], acc[mt][nt][3]);
        }
}

// ---------------- RoPE + transpose ----------------
__global__ void rope_kernel(const float* __restrict__ cosT, const float* __restrict__ sinT)
{
    const int qi   = blockIdx.x;
    const int slot = blockIdx.y;
    const int d    = threadIdx.x;
    const int pos  = PAST + qi;
    const float c = cosT[pos * HD + d];
    const float s = sinT[pos * HD + d];

    if (slot < NH) {
        const int h = slot;
        const float* src = g_qbuf + (size_t)qi * (NH * HD) + h * HD;
        float x = src[d], y = src[d ^ 64];
        g_qt[((size_t)h * B_Q + qi) * HD + d] = x * c + ((d < 64) ? -y : y) * s;
    } else if (slot < NH + NKV) {
        const int h = slot - NH;
        const float* src = g_kbuf + (size_t)qi * (NKV * HD) + h * HD;
        float x = src[d], y = src[d ^ 64];
        g_kt[((size_t)h * B_Q + qi) * HD + d] = x * c + ((d < 64) ? -y : y) * s;
    } else {
        const int h = slot - NH - NKV;
        g_vt[((size_t)h * B_Q + qi) * HD + d] =
            g_vbuf[(size_t)qi * (NKV * HD) + h * HD + d];
    }
}

// ---------------- Flash attention, tf32 mma ----------------
// 128 threads = 4 warps. Warp w owns query rows [w*16, w*16+16) x ALL 128 keys
// -> softmax reductions are full-row quad shuffles (no cross-warp state).
// Q-tile 64, K-tile 128. Kept-key map j -> (j<4 ? j : j+1024); mask j <= 3072+q.
__global__ __launch_bounds__(128) void attn_tc(
    const float* __restrict__ pk, const float* __restrict__ pv)
{
    extern __shared__ float sm[];
    float (*Qs)[132] = (float(*)[132])sm;                              // 64 x 128
    float (*Ks)[132] = (float(*)[132])(sm + 64 * 132);                 // 128 x 128
    float (*Vs)[132] = (float(*)[132])(sm + 64 * 132 + 128 * 132);     // 128 x 128
    float (*Ps)[132] = (float(*)[132])(sm + 64 * 132 + 2 * 128 * 132); // 64 x 128

    const int tid = threadIdx.x;
    const int w = tid >> 5, lane = tid & 31;
    const int g = lane >> 2, cq = lane & 3;
    const int q0 = blockIdx.x * 64;
    const int h  = blockIdx.y;
    const int kvh = h >> 2;
    const int rbase = w * 16;           // warp's first local row

    // Q tile (64 rows x 128 d)
#pragma unroll
    for (int p = 0; p < 16; p++) {
        int e = p * 128 + tid;
        int row = e >> 5, d4 = (e & 31) * 4;
        float4 v = *(const float4*)&g_qt[((size_t)h * B_Q + q0 + row) * HD + d4];
        *(float4*)&Qs[row][d4] = make_float4(f2tff(v.x), f2tff(v.y), f2tff(v.z), f2tff(v.w));
    }

    float m_i[2], l_i[2];
    float o[16][4];
    m_i[0] = m_i[1] = -1e30f;
    l_i[0] = l_i[1] = 0.f;
#pragma unroll
    for (int nt = 0; nt < 16; nt++)
#pragma unroll
        for (int r = 0; r < 4; r++) o[nt][r] = 0.f;

    const int ntiles = ((3072 + q0 + 63) >> 7) + 1;

    for (int kt = 0; kt < ntiles; kt++) {
        const int jbase = kt * 128;
        __syncthreads();   // prior PV reads done before overwrite

        // K & V tiles (128 x 128 each)
#pragma unroll
        for (int p = 0; p < 32; p++) {
            int e = p * 128 + tid;
            int row = e >> 5, d4 = (e & 31) * 4;
            int j = jbase + row;
            int kp = (j < SINKS_N) ? j : j + 1024;
            const float* sk = (kp < PAST)
                ? &pk[((size_t)kvh * PAST + kp) * HD + d4]
                : &g_kt[((size_t)kvh * B_Q + (kp - PAST)) * HD + d4];
            const float* sv = (kp < PAST)
                ? &pv[((size_t)kvh * PAST + kp) * HD + d4]
                : &g_vt[((size_t)kvh * B_Q + (kp - PAST)) * HD + d4];
            float4 kv4 = *(const float4*)sk;
            float4 vv4 = *(const float4*)sv;
            *(float4*)&Ks[row][d4] = make_float4(f2tff(kv4.x), f2tff(kv4.y), f2tff(kv4.z), f2tff(kv4.w));
            *(float4*)&Vs[row][d4] = make_float4(f2tff(vv4.x), f2tff(vv4.y), f2tff(vv4.z), f2tff(vv4.w));
        }
        __syncthreads();

        // ---- S = Q @ K^T : warp tile 16 rows x 128 keys ----
        float s[16][4];
#pragma unroll
        for (int nt = 0; nt < 16; nt++)
#pragma unroll
            for (int r = 0; r < 4; r++) s[nt][r] = 0.f;

#pragma unroll
        for (int ks = 0; ks < 16; ks++) {
            const int k = ks * 8 + cq;
            unsigned a0 = __float_as_uint(Qs[rbase + g][k]);
            unsigned a1 = __float_as_uint(Qs[rbase + g + 8][k]);
            unsigned a2 = __float_as_uint(Qs[rbase + g][k + 4]);
            unsigned a3 = __float_as_uint(Qs[rbase + g + 8][k + 4]);
#pragma unroll
            for (int nt = 0; nt < 16; nt++) {
                unsigned b0 = __float_as_uint(Ks[nt * 8 + g][k]);
                unsigned b1 = __float_as_uint(Ks[nt * 8 + g][k + 4]);
                mma_tf32(s[nt], a0, a1, a2, a3, b0, b1);
            }
        }

        // ---- online softmax: rows rbase+g (half 0) and rbase+g+8 (half 1) ----
#pragma unroll
        for (int half = 0; half < 2; half++) {
            const int rl  = rbase + g + half * 8;
            const int lim = 3072 + q0 + rl;
            float mx = -1e30f;
#pragma unroll
            for (int nt = 0; nt < 16; nt++)
#pragma unroll
                for (int rr = 0; rr < 2; rr++) {
                    int jg = jbase + nt * 8 + 2 * cq + rr;
                    float v = (jg <= lim) ? s[nt][half * 2 + rr] * SCALE_QK : -1e30f;
                    s[nt][half * 2 + rr] = v;
                    mx = fmaxf(mx, v);
                }
            mx = fmaxf(mx, __shfl_xor_sync(0xffffffffu, mx, 1));
            mx = fmaxf(mx, __shfl_xor_sync(0xffffffffu, mx, 2));
            float mnew = fmaxf(m_i[half], mx);
            float corr = __expf(m_i[half] - mnew);
            m_i[half] = mnew;
            float rs = 0.f;
#pragma unroll
            for (int nt = 0; nt < 16; nt++) {
                float p0 = __expf(s[nt][half * 2]     - mnew);
                float p1 = __expf(s[nt][half * 2 + 1] - mnew);
                rs += p0 + p1;
                *(float2*)&Ps[rl][nt * 8 + 2 * cq] = make_float2(f2tff(p0), f2tff(p1));
            }
            rs += __shfl_xor_sync(0xffffffffu, rs, 1);
            rs += __shfl_xor_sync(0xffffffffu, rs, 2);
            l_i[half] = l_i[half] * corr + rs;
#pragma unroll
            for (int nt = 0; nt < 16; nt++) {
                o[nt][half * 2]     *= corr;
                o[nt][half * 2 + 1] *= corr;
            }
        }
        __syncthreads();   // Ps visible to all warps (each reads only its rows, but keep ordered with next overwrite)

        // ---- O += P @ V : warp tile 16 rows x 128 d ----
#pragma unroll
        for (int ks = 0; ks < 16; ks++) {
            const int k = ks * 8 + cq;
            unsigned a0 = __float_as_uint(Ps[rbase + g][k]);
            unsigned a1 = __float_as_uint(Ps[rbase + g + 8][k]);
            unsigned a2 = __float_as_uint(Ps[rbase + g][k + 4]);
            unsigned a3 = __float_as_uint(Ps[rbase + g + 8][k + 4]);
#pragma unroll
            for (int nt = 0; nt < 16; nt++) {
                unsigned b0 = __float_as_uint(Vs[k][nt * 8 + g]);
                unsigned b1 = __float_as_uint(Vs[k + 4][nt * 8 + g]);
                mma_tf32(o[nt], a0, a1, a2, a3, b0, b1);
            }
        }
    }

    // ---- epilogue ----
    float inv0 = 1.0f / l_i[0];
    float inv1 = 1.0f / l_i[1];
    int row0 = q0 + rbase + g;
#pragma unroll
    for (int nt = 0; nt < 16; nt++) {
        int dd = nt * 8 + 2 * cq;
        *(float2*)&g_attn[(size_t)row0 * (NH * HD) + h * HD + dd] =
            make_float2(o[nt][0] * inv0, o[nt][1] * inv0);
        *(float2*)&g_attn[(size_t)(row0 + 8) * (NH * HD) + h * HD + dd] =
            make_float2(o[nt][2] * inv1, o[nt][3] * inv1);
    }
}

// ---------------- launch ----------------
extern "C" void kernel_launch(void* const* d_in, const int* in_sizes, int n_in,
                              void* d_out, int out_size)
{
    (void)in_sizes; (void)n_in; (void)out_size;
    const float* hidden = (const float*)d_in[0];
    const float* Wq     = (const float*)d_in[1];
    const float* Wk     = (const float*)d_in[2];
    const float* Wv     = (const float*)d_in[3];
    const float* Wo     = (const float*)d_in[4];
    const float* past_k = (const float*)d_in[5];
    const float* past_v = (const float*)d_in[6];
    const float* cosT   = (const float*)d_in[7];
    const float* sinT   = (const float*)d_in[8];

    void *p_qbuf, *p_kbuf, *p_vbuf, *p_attn;
    cudaGetSymbolAddress(&p_qbuf, g_qbuf);
    cudaGetSymbolAddress(&p_kbuf, g_kbuf);
    cudaGetSymbolAddress(&p_vbuf, g_vbuf);
    cudaGetSymbolAddress(&p_attn, g_attn);

    const int attn_smem = (64 * 132 + 128 * 132 + 128 * 132 + 64 * 132) * 4; // 202752 B
    cudaFuncSetAttribute(attn_tc, cudaFuncAttributeMaxDynamicSharedMemorySize, attn_smem);

    dim3 blk(256);
    sgemm_tc<<<dim3(DM / 128, B_Q / 128), blk>>>(hidden, Wq, (float*)p_qbuf, B_Q, DM, DM);
    sgemm_tc<<<dim3((NKV * HD) / 128, B_Q / 128), blk>>>(hidden, Wk, (float*)p_kbuf, B_Q, NKV * HD, DM);
    sgemm_tc<<<dim3((NKV * HD) / 128, B_Q / 128), blk>>>(hidden, Wv, (float*)p_vbuf, B_Q, NKV * HD, DM);
    rope_kernel<<<dim3(B_Q, NH + 2 * NKV), 128>>>(cosT, sinT);
    attn_tc<<<dim3(B_Q / 64, NH), 128, attn_smem>>>(past_k, past_v);
    sgemm_tc<<<dim3(DM / 128, B_Q / 128), blk>>>((const float*)p_attn, Wo, (float*)d_out, B_Q, DM, NH * HD);
}

// round 5
// speedup vs baseline: 2.9347x; 1.4269x over previous
#include <cuda_runtime.h>
#include <cuda_bf16.h>
#include <cstdint>
#include <math.h>

// ---------------- problem constants ----------------
#define B_Q     1024
#define DM      4096
#define NH      32
#define NKV     8
#define HD      128
#define PAST    4096
#define SINKS_N 4
#define SCALE_QK 0.08838834764831845f   // 1/sqrt(128)

// ---------------- scratch ----------------
__device__ float g_qbuf[B_Q * NH * HD];
__device__ float g_kbuf[B_Q * NKV * HD];
__device__ float g_vbuf[B_Q * NKV * HD];
__device__ float g_qt[NH * B_Q * HD];
__device__ float g_kt[NKV * B_Q * HD];
__device__ float g_vt[NKV * B_Q * HD];
__device__ float g_attn[B_Q * NH * HD];

// ---------------- helpers ----------------
__device__ __forceinline__ uint32_t smem_u32(const void* p) {
    uint32_t a;
    asm("{ .reg .u64 t; cvta.to.shared.u64 t, %1; cvt.u32.u64 %0, t; }" : "=r"(a) : "l"(p));
    return a;
}
__device__ __forceinline__ unsigned f2tf(float x) {
    unsigned u; asm("cvt.rna.tf32.f32 %0, %1;" : "=r"(u) : "f"(x)); return u;
}
__device__ __forceinline__ float f2tff(float x) { return __uint_as_float(f2tf(x)); }

__device__ __forceinline__ void mma_tf32(float d[4],
    unsigned a0, unsigned a1, unsigned a2, unsigned a3, unsigned b0, unsigned b1)
{
    asm volatile(
        "mma.sync.aligned.m16n8k8.row.col.f32.tf32.tf32.f32 "
        "{%0,%1,%2,%3},{%4,%5,%6,%7},{%8,%9},{%0,%1,%2,%3};"
        : "+f"(d[0]), "+f"(d[1]), "+f"(d[2]), "+f"(d[3])
        : "r"(a0), "r"(a1), "r"(a2), "r"(a3), "r"(b0), "r"(b1));
}
// ldmatrix x4: lanes 0-7 -> matrix0 rows, 8-15 -> m1, 16-23 -> m2, 24-31 -> m3.
// For tf32 A-frag: m0=(rows 0-7, k..k+3), m1=(rows 8-15, k..k+3), m2=(rows0-7,k+4..), m3=(rows8-15,k+4..)
__device__ __forceinline__ void ldm_x4(unsigned a[4], uint32_t addr) {
    asm volatile("ldmatrix.sync.aligned.m8n8.x4.shared.b16 {%0,%1,%2,%3}, [%4];"
        : "=r"(a[0]), "=r"(a[1]), "=r"(a[2]), "=r"(a[3]) : "r"(addr));
}

// ---------------- tf32 tensor-core SGEMM ----------------
// C[M,N]=A[M,K]@B[K,N] row-major. Block 128x128, k-stage 32, 8 warps (2x4),
// warp tile 64x32. Register-prefetch + double smem buffer (1 bar/stage).
// A-fragments via ldmatrix.x4; B scalar (k-major, conflict-free).
__global__ __launch_bounds__(256, 2) void sgemm_tc(
    const float* __restrict__ A, const float* __restrict__ B,
    float* __restrict__ C, int M, int N, int K)
{
    extern __shared__ float smg[];
    float* As[2] = { smg, smg + 128 * 36 };
    float* Bs[2] = { smg + 2 * 128 * 36, smg + 2 * 128 * 36 + 32 * 132 };

    const int tid  = threadIdx.x;
    const int w    = tid >> 5, lane = tid & 31;
    const int g    = lane >> 2, cq = lane & 3;
    const int wm   = w & 1, wn = w >> 1;
    const int m0   = blockIdx.y * 128, n0 = blockIdx.x * 128;

    const int ar  = tid >> 3, ac4 = (tid & 7) * 4;
    const int bkr = tid >> 5, bn4 = (tid & 31) * 4;

    // per-lane ldmatrix row/col offset (in words) for A-frag, per mt
    const int lrow = ((lane >> 3) & 1) * 8 + (lane & 7);
    const int lcol = (lane >> 4) * 4;
    int aoff[4];
#pragma unroll
    for (int mt = 0; mt < 4; mt++)
        aoff[mt] = ((wm * 64 + mt * 16 + lrow) * 36 + lcol) * 4;
    const uint32_t as_u[2] = { smem_u32(As[0]), smem_u32(As[1]) };

    float acc[4][4][4];
#pragma unroll
    for (int i = 0; i < 4; i++)
#pragma unroll
        for (int j = 0; j < 4; j++)
#pragma unroll
            for (int r = 0; r < 4; r++) acc[i][j][r] = 0.f;

    const int ns = K >> 5;
    float4 ra[4], rb[4];
    // prologue: load stage 0
#pragma unroll
    for (int p = 0; p < 4; p++) {
        ra[p] = *(const float4*)&A[(size_t)(m0 + ar + p * 32) * K + ac4];
        rb[p] = *(const float4*)&B[(size_t)(bkr + p * 8) * N + n0 + bn4];
    }

    for (int i = 0; i < ns; i++) {
        float* Ab = As[i & 1];
        float* Bb = Bs[i & 1];
        const uint32_t abu = as_u[i & 1];
#pragma unroll
        for (int p = 0; p < 4; p++) {
            *(float4*)&Ab[(ar + p * 32) * 36 + ac4] =
                make_float4(f2tff(ra[p].x), f2tff(ra[p].y), f2tff(ra[p].z), f2tff(ra[p].w));
            *(float4*)&Bb[(bkr + p * 8) * 132 + bn4] =
                make_float4(f2tff(rb[p].x), f2tff(rb[p].y), f2tff(rb[p].z), f2tff(rb[p].w));
        }
        __syncthreads();

        if (i + 1 < ns) {
            const int k0 = (i + 1) * 32;
#pragma unroll
            for (int p = 0; p < 4; p++) {
                ra[p] = *(const float4*)&A[(size_t)(m0 + ar + p * 32) * K + k0 + ac4];
                rb[p] = *(const float4*)&B[(size_t)(k0 + bkr + p * 8) * N + n0 + bn4];
            }
        }

#pragma unroll
        for (int ks = 0; ks < 4; ks++) {
            const int k = ks * 8 + cq;
            unsigned a[4][4], b[4][2];
#pragma unroll
            for (int mt = 0; mt < 4; mt++)
                ldm_x4(a[mt], abu + aoff[mt] + ks * 32);
#pragma unroll
            for (int nt = 0; nt < 4; nt++) {
                int n = wn * 32 + nt * 8 + g;
                b[nt][0] = __float_as_uint(Bb[k * 132 + n]);
                b[nt][1] = __float_as_uint(Bb[(k + 4) * 132 + n]);
            }
#pragma unroll
            for (int mt = 0; mt < 4; mt++)
#pragma unroll
                for (int nt = 0; nt < 4; nt++)
                    mma_tf32(acc[mt][nt], a[mt][0], a[mt][1], a[mt][2], a[mt][3],
                             b[nt][0], b[nt][1]);
        }
    }

#pragma unroll
    for (int mt = 0; mt < 4; mt++)
#pragma unroll
        for (int nt = 0; nt < 4; nt++) {
            int r  = m0 + wm * 64 + mt * 16 + g;
            int cc = n0 + wn * 32 + nt * 8 + 2 * cq;
            *(float2*)&C[(size_t)r * N + cc]       = make_float2(acc[mt][nt][0], acc[mt][nt][1]);
            *(float2*)&C[(size_t)(r + 8) * N + cc] = make_float2(acc[mt][nt][2], acc[mt][nt][3]);
        }
}

// ---------------- RoPE + transpose ----------------
__global__ void rope_kernel(const float* __restrict__ cosT, const float* __restrict__ sinT)
{
    const int qi   = blockIdx.x;
    const int slot = blockIdx.y;
    const int d    = threadIdx.x;
    const int pos  = PAST + qi;
    const float c = cosT[pos * HD + d];
    const float s = sinT[pos * HD + d];

    if (slot < NH) {
        const int h = slot;
        const float* src = g_qbuf + (size_t)qi * (NH * HD) + h * HD;
        float x = src[d], y = src[d ^ 64];
        g_qt[((size_t)h * B_Q + qi) * HD + d] = x * c + ((d < 64) ? -y : y) * s;
    } else if (slot < NH + NKV) {
        const int h = slot - NH;
        const float* src = g_kbuf + (size_t)qi * (NKV * HD) + h * HD;
        float x = src[d], y = src[d ^ 64];
        g_kt[((size_t)h * B_Q + qi) * HD + d] = x * c + ((d < 64) ? -y : y) * s;
    } else {
        const int h = slot - NH - NKV;
        g_vt[((size_t)h * B_Q + qi) * HD + d] =
            g_vbuf[(size_t)qi * (NKV * HD) + h * HD + d];
    }
}

// ---------------- Flash attention, tf32 mma ----------------
// 256 threads = 8 warps. Q-tile 128 (warp w owns rows w*16..+15), K-tile 64.
// Ps is warp-private -> __syncwarp only after softmax. ldmatrix for Q/P A-frags.
__global__ __launch_bounds__(256) void attn_tc(
    const float* __restrict__ pk, const float* __restrict__ pv)
{
    extern __shared__ float sm[];
    float (*Qs)[132] = (float(*)[132])sm;                            // 128 x 132
    float (*Ks)[132] = (float(*)[132])(sm + 128 * 132);              // 64 x 132
    float (*Vs)[132] = (float(*)[132])(sm + 128 * 132 + 64 * 132);   // 64 x 132
    float (*Ps)[68]  = (float(*)[68]) (sm + 128 * 132 + 2 * 64 * 132); // 128 x 68

    const int tid = threadIdx.x;
    const int w = tid >> 5, lane = tid & 31;
    const int g = lane >> 2, cq = lane & 3;
    const int q0 = blockIdx.x * 128;
    const int h  = blockIdx.y;
    const int kvh = h >> 2;
    const int rbase = w * 16;

    // ldmatrix per-lane addresses (A-fragments from Qs and Ps)
    const int lrow = rbase + ((lane >> 3) & 1) * 8 + (lane & 7);
    const int lcol = (lane >> 4) * 4;
    const uint32_t qmat = smem_u32(&Qs[0][0]) + (lrow * 132 + lcol) * 4;
    const uint32_t pmat = smem_u32(&Ps[0][0]) + (lrow * 68 + lcol) * 4;

    // Q tile: 128 rows x 128 d
#pragma unroll
    for (int p = 0; p < 16; p++) {
        int e = p * 256 + tid;
        int row = e >> 5, d4 = (e & 31) * 4;
        float4 v = *(const float4*)&g_qt[((size_t)h * B_Q + q0 + row) * HD + d4];
        *(float4*)&Qs[row][d4] = make_float4(f2tff(v.x), f2tff(v.y), f2tff(v.z), f2tff(v.w));
    }

    float m_i[2], l_i[2];
    float o[16][4];
    m_i[0] = m_i[1] = -1e30f;
    l_i[0] = l_i[1] = 0.f;
#pragma unroll
    for (int nt = 0; nt < 16; nt++)
#pragma unroll
        for (int r = 0; r < 4; r++) o[nt][r] = 0.f;

    const int ntiles = ((3072 + q0 + 127) >> 6) + 1;

    for (int kt = 0; kt < ntiles; kt++) {
        const int jbase = kt * 64;
        __syncthreads();   // prior S/PV reads of Ks/Vs done (also covers Q store at kt=0)

        // K & V tiles (64 x 128 each)
#pragma unroll
        for (int p = 0; p < 8; p++) {
            int e = p * 256 + tid;
            int row = e >> 5, d4 = (e & 31) * 4;
            int j = jbase + row;
            int kp = (j < SINKS_N) ? j : j + 1024;
            const float* sk = (kp < PAST)
                ? &pk[((size_t)kvh * PAST + kp) * HD + d4]
                : &g_kt[((size_t)kvh * B_Q + (kp - PAST)) * HD + d4];
            const float* sv = (kp < PAST)
                ? &pv[((size_t)kvh * PAST + kp) * HD + d4]
                : &g_vt[((size_t)kvh * B_Q + (kp - PAST)) * HD + d4];
            float4 kv4 = *(const float4*)sk;
            float4 vv4 = *(const float4*)sv;
            *(float4*)&Ks[row][d4] = make_float4(f2tff(kv4.x), f2tff(kv4.y), f2tff(kv4.z), f2tff(kv4.w));
            *(float4*)&Vs[row][d4] = make_float4(f2tff(vv4.x), f2tff(vv4.y), f2tff(vv4.z), f2tff(vv4.w));
        }
        __syncthreads();

        // ---- S = Q @ K^T : 16 rows x 64 keys per warp ----
        float s[8][4];
#pragma unroll
        for (int nt = 0; nt < 8; nt++)
#pragma unroll
            for (int r = 0; r < 4; r++) s[nt][r] = 0.f;

#pragma unroll
        for (int ks = 0; ks < 16; ks++) {
            const int k = ks * 8 + cq;
            unsigned a[4];
            ldm_x4(a, qmat + ks * 32);
#pragma unroll
            for (int nt = 0; nt < 8; nt++) {
                unsigned b0 = __float_as_uint(Ks[nt * 8 + g][k]);
                unsigned b1 = __float_as_uint(Ks[nt * 8 + g][k + 4]);
                mma_tf32(s[nt], a[0], a[1], a[2], a[3], b0, b1);
            }
        }

        // ---- online softmax ----
#pragma unroll
        for (int half = 0; half < 2; half++) {
            const int rl  = rbase + g + half * 8;
            const int lim = 3072 + q0 + rl;
            float mx = -1e30f;
#pragma unroll
            for (int nt = 0; nt < 8; nt++)
#pragma unroll
                for (int rr = 0; rr < 2; rr++) {
                    int jg = jbase + nt * 8 + 2 * cq + rr;
                    float v = (jg <= lim) ? s[nt][half * 2 + rr] * SCALE_QK : -1e30f;
                    s[nt][half * 2 + rr] = v;
                    mx = fmaxf(mx, v);
                }
            mx = fmaxf(mx, __shfl_xor_sync(0xffffffffu, mx, 1));
            mx = fmaxf(mx, __shfl_xor_sync(0xffffffffu, mx, 2));
            float mnew = fmaxf(m_i[half], mx);
            float corr = __expf(m_i[half] - mnew);
            m_i[half] = mnew;
            float rs = 0.f;
#pragma unroll
            for (int nt = 0; nt < 8; nt++) {
                float p0 = __expf(s[nt][half * 2]     - mnew);
                float p1 = __expf(s[nt][half * 2 + 1] - mnew);
                rs += p0 + p1;
                *(float2*)&Ps[rl][nt * 8 + 2 * cq] = make_float2(f2tff(p0), f2tff(p1));
            }
            rs += __shfl_xor_sync(0xffffffffu, rs, 1);
            rs += __shfl_xor_sync(0xffffffffu, rs, 2);
            l_i[half] = l_i[half] * corr + rs;
#pragma unroll
            for (int nt = 0; nt < 16; nt++) {
                o[nt][half * 2]     *= corr;
                o[nt][half * 2 + 1] *= corr;
            }
        }
        __syncwarp();   // Ps is warp-private: lane-cross visibility only

        // ---- O += P @ V : 16 rows x 128 d per warp, k-dim 64 ----
#pragma unroll
        for (int ks = 0; ks < 8; ks++) {
            const int k = ks * 8 + cq;
            unsigned a[4];
            ldm_x4(a, pmat + ks * 32);
#pragma unroll
            for (int nt = 0; nt < 16; nt++) {
                unsigned b0 = __float_as_uint(Vs[k][nt * 8 + g]);
                unsigned b1 = __float_as_uint(Vs[k + 4][nt * 8 + g]);
                mma_tf32(o[nt], a[0], a[1], a[2], a[3], b0, b1);
            }
        }
    }

    // ---- epilogue ----
    float inv0 = 1.0f / l_i[0];
    float inv1 = 1.0f / l_i[1];
    int row0 = q0 + rbase + g;
#pragma unroll
    for (int nt = 0; nt < 16; nt++) {
        int dd = nt * 8 + 2 * cq;
        *(float2*)&g_attn[(size_t)row0 * (NH * HD) + h * HD + dd] =
            make_float2(o[nt][0] * inv0, o[nt][1] * inv0);
        *(float2*)&g_attn[(size_t)(row0 + 8) * (NH * HD) + h * HD + dd] =
            make_float2(o[nt][2] * inv1, o[nt][3] * inv1);
    }
}

// ---------------- launch ----------------
extern "C" void kernel_launch(void* const* d_in, const int* in_sizes, int n_in,
                              void* d_out, int out_size)
{
    (void)in_sizes; (void)n_in; (void)out_size;
    const float* hidden = (const float*)d_in[0];
    const float* Wq     = (const float*)d_in[1];
    const float* Wk     = (const float*)d_in[2];
    const float* Wv     = (const float*)d_in[3];
    const float* Wo     = (const float*)d_in[4];
    const float* past_k = (const float*)d_in[5];
    const float* past_v = (const float*)d_in[6];
    const float* cosT   = (const float*)d_in[7];
    const float* sinT   = (const float*)d_in[8];

    void *p_qbuf, *p_kbuf, *p_vbuf, *p_attn;
    cudaGetSymbolAddress(&p_qbuf, g_qbuf);
    cudaGetSymbolAddress(&p_kbuf, g_kbuf);
    cudaGetSymbolAddress(&p_vbuf, g_vbuf);
    cudaGetSymbolAddress(&p_attn, g_attn);

    const int gemm_smem = (2 * 128 * 36 + 2 * 32 * 132) * 4;   // 70656 B
    cudaFuncSetAttribute(sgemm_tc, cudaFuncAttributeMaxDynamicSharedMemorySize, gemm_smem);
    const int attn_smem = (128 * 132 + 64 * 132 + 64 * 132 + 128 * 68) * 4; // 169984 B
    cudaFuncSetAttribute(attn_tc, cudaFuncAttributeMaxDynamicSharedMemorySize, attn_smem);

    dim3 blk(256);
    sgemm_tc<<<dim3(DM / 128, B_Q / 128), blk, gemm_smem>>>(hidden, Wq, (float*)p_qbuf, B_Q, DM, DM);
    sgemm_tc<<<dim3((NKV * HD) / 128, B_Q / 128), blk, gemm_smem>>>(hidden, Wk, (float*)p_kbuf, B_Q, NKV * HD, DM);
    sgemm_tc<<<dim3((NKV * HD) / 128, B_Q / 128), blk, gemm_smem>>>(hidden, Wv, (float*)p_vbuf, B_Q, NKV * HD, DM);
    rope_kernel<<<dim3(B_Q, NH + 2 * NKV), 128>>>(cosT, sinT);
    attn_tc<<<dim3(B_Q / 128, NH), blk, attn_smem>>>(past_k, past_v);
    sgemm_tc<<<dim3(DM / 128, B_Q / 128), blk, gemm_smem>>>((const float*)p_attn, Wo, (float*)d_out, B_Q, DM, NH * HD);
}